// round 12
// baseline (speedup 1.0000x reference)
#include <cuda_runtime.h>

// Reference semantics reduce to (softmax over a size-1 axis == 1; W is dead code):
//   out[i, 0:512]    = 2*X[i]                              for i < 64
//   out[i, 0:512]    = X[i] + sum_{r=i-64..i-1} X[r]       for i >= 64
//   out[i, 512:1024] = X[i]
//
// Single fused kernel. Block = 256 threads = (chunk k of 64 output rows) x
// (8 f4 columns). 32 segments x 4 rows = loaded rows [64(k-1), 64k+64).
// Thread = (segment s = tid>>3, col c = tid&7); 4 rows per thread -> small
// register state -> high occupancy. Prefix over segments is hierarchical:
// shfl-scan inside each warp (4 segs), only 8 warp totals via smem.
// Upper warps (s>=16) own the output rows they loaded: right-half copy issues
// from registers pre-barrier; left half H = v[j] + (acc - Plow[m-64]).

#define NROWS 4096
#define DCOLS 512
#define LENS  64
#define D4    (DCOLS / 4)    // 128 f4 per input row
#define OD4   (2 * D4)       // 256 f4 per output row
#define CPB   8              // f4 columns per block
#define NG    (D4 / CPB)     // 16 column groups
#define NCH   (NROWS / LENS) // 64 chunks
#define SEG   4              // rows per thread
#define NWARP 8

static __device__ __forceinline__ float4 f4add(float4 a, float4 b) {
    return make_float4(a.x + b.x, a.y + b.y, a.z + b.z, a.w + b.w);
}
static __device__ __forceinline__ float4 f4sub(float4 a, float4 b) {
    return make_float4(a.x - b.x, a.y - b.y, a.z - b.z, a.w - b.w);
}
static __device__ __forceinline__ float4 shfl_up4(float4 v, int d) {
    float4 r;
    r.x = __shfl_up_sync(0xffffffffu, v.x, d);
    r.y = __shfl_up_sync(0xffffffffu, v.y, d);
    r.z = __shfl_up_sync(0xffffffffu, v.z, d);
    r.w = __shfl_up_sync(0xffffffffu, v.w, d);
    return r;
}

__global__ __launch_bounds__(256, 5) void fused_window_kernel(
    const float4* __restrict__ X4, float4* __restrict__ O4)
{
    const int b    = blockIdx.x;
    const int k    = b >> 4;           // chunk 0..63
    const int g    = b & 15;           // column group 0..15
    const int tid  = threadIdx.x;
    const int c    = tid & 7;          // column within group
    const int col  = g * CPB + c;      // global f4 column
    const int s    = tid >> 3;         // segment 0..31
    const int w    = tid >> 5;         // warp 0..7
    const int lane = tid & 31;

    if (k == 0) {
        // rows 0..63: left = 2X, right = X. Thread handles rows s*2, s*2+1.
        #pragma unroll
        for (int r = 0; r < 2; ++r) {
            const int i = s * 2 + r;
            float4 x = X4[(size_t)i * D4 + col];
            O4[(size_t)i * OD4 + col]      = f4add(x, x);
            O4[(size_t)i * OD4 + D4 + col] = x;
        }
        return;
    }

    __shared__ float4 wtot[NWARP * CPB];  // per-warp totals (512 B)
    __shared__ float4 Plow[LENS * CPB];   // exclusive prefix P[0..63] (4 KB)

    // ---- Load: 4 independent LDG.128 per thread; rows base + s*4 + j ----
    const int base = (k - 1) * LENS;
    const float4* px = X4 + (size_t)(base + s * SEG) * D4 + col;
    float4 v[SEG];
    #pragma unroll
    for (int j = 0; j < SEG; ++j) v[j] = px[(size_t)j * D4];

    // Upper warps (s >= 16): right-half copy from registers, pre-barrier.
    if (s >= 16) {
        float4* po = O4 + (size_t)(base + s * SEG) * OD4 + D4 + col;
        #pragma unroll
        for (int j = 0; j < SEG; ++j)
            po[(size_t)j * OD4] = v[j];
    }

    // Segment total (tree of 4).
    float4 ls = f4add(f4add(v[0], v[1]), f4add(v[2], v[3]));

    // Within-warp inclusive scan over 4 segments (stride 8, then 16).
    float4 inc = ls;
    {
        float4 t = shfl_up4(inc, 8);
        if (lane >= 8) inc = f4add(inc, t);
        t = shfl_up4(inc, 16);
        if (lane >= 16) inc = f4add(inc, t);
    }

    // Warp total -> smem (last segment's inclusive value).
    if (lane >= 24) wtot[w * CPB + c] = inc;
    __syncthreads();

    // Cross-warp offset: sum of warp totals below w (7 predicated LDS).
    float4 off = f4sub(inc, ls);          // within-warp exclusive
    #pragma unroll
    for (int j = 0; j < NWARP - 1; ++j) {
        float4 t = wtot[j * CPB + c];
        if (w > j) off = f4add(off, t);
    }

    if (s < 16) {
        // Lower warps: publish exclusive prefixes P[s*4+j].
        float4 acc = off;
        float4* pp = Plow + (s * SEG) * CPB + c;
        #pragma unroll
        for (int j = 0; j < SEG; ++j) {
            pp[j * CPB] = acc;
            acc = f4add(acc, v[j]);
        }
        __syncthreads();
    } else {
        __syncthreads();
        // Upper warps: emit left half. Loaded row m = s*4+j; output row i = base+m.
        //   W = P[m] - Plow[m-64],  P[m] = acc before adding v[j].
        float4 acc = off;
        const float4* pl = Plow + ((s - 16) * SEG) * CPB + c;
        float4* po = O4 + (size_t)(base + s * SEG) * OD4 + col;
        #pragma unroll
        for (int j = 0; j < SEG; ++j) {
            float4 wsum = f4sub(acc, pl[j * CPB]);
            po[(size_t)j * OD4] = f4add(v[j], wsum);
            acc = f4add(acc, v[j]);
        }
    }
}

extern "C" void kernel_launch(void* const* d_in, const int* in_sizes, int n_in,
                              void* d_out, int out_size)
{
    const float4* X4 = (const float4*)d_in[0];   // X: (4096, 512) f32
    float4* O4 = (float4*)d_out;                 // out: (4096, 1024) f32

    fused_window_kernel<<<NCH * NG, 256>>>(X4, O4);   // 1024 blocks, 1 launch
}